// round 16
// baseline (speedup 1.0000x reference)
#include <cuda_runtime.h>
#include <math.h>
#include <stdint.h>

// Problem dims (fixed by the dataset)
#define BB   32
#define LL   256
#define DD   1024
#define MTOT (BB*LL)      // 8192 tokens
#define K1   (15*DD)      // 15360
#define N2   (4*DD)       // 4096
#define EPSV 1e-5f

#define NWG (DD*K1)       // 15,728,640
#define NW1 (N2*DD)       // 4,194,304
#define NW2 (DD*N2)       // 4,194,304

// ---------------- scratch (device globals; no allocation allowed) -----------
__device__ float g_xn[MTOT*DD];
__device__ float g_rowmax[MTOT];
__device__ float g_xs[MTOT];
__device__ float g_hs[MTOT];
__device__ float g_gs[MTOT];
__device__ float g_xres[MTOT*DD];
__device__ float g_gelu[MTOT*N2];
__device__ __align__(16) signed char g_cq[(size_t)MTOT*K1];
__device__ __align__(16) signed char g_hq[(size_t)MTOT*DD];
__device__ __align__(16) signed char g_gq[(size_t)MTOT*N2];
__device__ __align__(16) signed char g_wgq[(size_t)NWG];
__device__ __align__(16) signed char g_w1q[(size_t)NW1];
__device__ __align__(16) signed char g_w2q[(size_t)NW2];
__device__ float g_ws[3];
__device__ float g_part[3][512];

// ---------------- small helpers ---------------------------------------------
__device__ __forceinline__ float blockReduceSum256(float v, float* red) {
    int t = threadIdx.x;
    red[t] = v; __syncthreads();
    #pragma unroll
    for (int o = 128; o > 0; o >>= 1) {
        if (t < o) red[t] += red[t + o];
        __syncthreads();
    }
    float r = red[0]; __syncthreads();
    return r;
}
__device__ __forceinline__ float blockReduceMax256(float v, float* red) {
    int t = threadIdx.x;
    red[t] = v; __syncthreads();
    #pragma unroll
    for (int o = 128; o > 0; o >>= 1) {
        if (t < o) red[t] = fmaxf(red[t], red[t + o]);
        __syncthreads();
    }
    float r = red[0]; __syncthreads();
    return r;
}
__device__ __forceinline__ uint32_t smem_u32(const void* p) {
    return (uint32_t)__cvta_generic_to_shared(p);
}
// round-half-even quantize 4 floats to [-128,127], pack to one int
__device__ __forceinline__ int quantPack4(float4 f, float s) {
    int a = min(max(__float2int_rn(f.x * s), -128), 127);
    int b = min(max(__float2int_rn(f.y * s), -128), 127);
    int c = min(max(__float2int_rn(f.z * s), -128), 127);
    int d = min(max(__float2int_rn(f.w * s), -128), 127);
    return (a & 255) | ((b & 255) << 8) | ((c & 255) << 16) | ((d & 255) << 24);
}

#define CP_ASYNC16(dst, src) \
    asm volatile("cp.async.cg.shared.global [%0], [%1], 16;\n" :: "r"(dst), "l"(src))
#define CP_COMMIT() asm volatile("cp.async.commit_group;\n" ::: "memory")
#define CP_WAIT0()  asm volatile("cp.async.wait_group 0;\n" ::: "memory")
#define CP_WAIT1()  asm volatile("cp.async.wait_group 1;\n" ::: "memory")

// ---------------- weight quantization (merged, 3 slots) ----------------------
// grid (512, 3): blockIdx.y = slot. Per-slot reduction order identical to the
// previous separate launches -> bit-identical g_ws.
__global__ void absmean_partial_all(const float* __restrict__ Wg,
                                    const float* __restrict__ W1,
                                    const float* __restrict__ W2) {
    __shared__ float red[256];
    int slot = blockIdx.y;
    const float* W = (slot == 0) ? Wg : (slot == 1) ? W1 : W2;
    int n = (slot == 0) ? NWG : (slot == 1) ? NW1 : NW2;
    float s = 0.f;
    for (int i = blockIdx.x * blockDim.x + threadIdx.x; i < n; i += 512 * blockDim.x)
        s += fabsf(W[i]);
    red[threadIdx.x] = s; __syncthreads();
    #pragma unroll
    for (int o = 128; o > 0; o >>= 1) {
        if (threadIdx.x < o) red[threadIdx.x] += red[threadIdx.x + o];
        __syncthreads();
    }
    if (threadIdx.x == 0) g_part[slot][blockIdx.x] = red[0];
}
// grid 3, block 512
__global__ void absmean_final_all() {
    __shared__ float red[512];
    int slot = blockIdx.x;
    red[threadIdx.x] = g_part[slot][threadIdx.x]; __syncthreads();
    #pragma unroll
    for (int o = 256; o > 0; o >>= 1) {
        if (threadIdx.x < o) red[threadIdx.x] += red[threadIdx.x + o];
        __syncthreads();
    }
    float invn = (slot == 0) ? (1.0f / (float)NWG)
               : (slot == 1) ? (1.0f / (float)NW1) : (1.0f / (float)NW2);
    if (threadIdx.x == 0) g_ws[slot] = red[0] * invn + EPSV;
}
// merged ternary quantization: one grid covering all three weight tensors
__global__ void quant_w_all(const float* __restrict__ Wg,
                            const float* __restrict__ W1,
                            const float* __restrict__ W2) {
    int i = (blockIdx.x * blockDim.x + threadIdx.x) * 4;
    const float* W;
    signed char* outp;
    float ws;
    if (i < NWG)                 { W = Wg;            outp = g_wgq;            ws = g_ws[0]; }
    else if (i < NWG + NW1)      { W = W1; i -= NWG;  outp = g_w1q;            ws = g_ws[1]; }
    else                         { W = W2; i -= NWG + NW1; outp = g_w2q;       ws = g_ws[2];
                                   if (i >= NW2) return; }
    float4 f = *(const float4*)(W + i);
    int a = min(max(__float2int_rn(f.x / ws), -1), 1);
    int b = min(max(__float2int_rn(f.y / ws), -1), 1);
    int c = min(max(__float2int_rn(f.z / ws), -1), 1);
    int d = min(max(__float2int_rn(f.w / ws), -1), 1);
    *(int*)&outp[i] = (a & 255) | ((b & 255) << 8) | ((c & 255) << 16) | ((d & 255) << 24);
}

// ---------------- LN1: stats + output + per-row max --------------------------
__global__ void ln1_kernel(const float* __restrict__ x,
                           const float* __restrict__ w,
                           const float* __restrict__ b) {
    __shared__ float red[256];
    int row = blockIdx.x;
    const float* xr = x + (size_t)row * DD;
    int d = threadIdx.x * 4;
    float4 f = *(const float4*)(xr + d);
    float s  = f.x + f.y + f.z + f.w;
    float s2 = f.x*f.x + f.y*f.y + f.z*f.z + f.w*f.w;
    s  = blockReduceSum256(s, red);
    s2 = blockReduceSum256(s2, red);
    float mean = s * (1.f / DD);
    float var  = fmaxf(s2 * (1.f / DD) - mean * mean, 0.f);
    float rstd = rsqrtf(var + EPSV);
    float4 wv = *(const float4*)(w + d);
    float4 bv = *(const float4*)(b + d);
    float4 y;
    y.x = (f.x - mean) * rstd * wv.x + bv.x;
    y.y = (f.y - mean) * rstd * wv.y + bv.y;
    y.z = (f.z - mean) * rstd * wv.z + bv.z;
    y.w = (f.w - mean) * rstd * wv.w + bv.w;
    *(float4*)&g_xn[(size_t)row * DD + d] = y;
    float mx = fmaxf(fmaxf(fabsf(y.x), fabsf(y.y)), fmaxf(fabsf(y.z), fabsf(y.w)));
    mx = blockReduceMax256(mx, red);
    if (threadIdx.x == 0) g_rowmax[row] = mx;
}

// ---------------- build quantized combined (scale computed inline) -----------
__global__ void buildc_kernel(const int* __restrict__ i0,
                              const int* __restrict__ i1,
                              const int* __restrict__ iv) {
    __shared__ float sxs;
    int bid = blockIdx.x;
    int tok = bid / 15, j = bid % 15;
    int bb = tok / LL, l = tok % LL;
    if (threadIdx.x == 0) {
        const float* rm = g_rowmax + bb * LL;
        float m = rm[l];
        #pragma unroll
        for (int k = 0; k < 3; k++) m = fmaxf(m, rm[i0[l * 3 + k]]);
        #pragma unroll
        for (int k = 0; k < 3; k++) m = fmaxf(m, rm[i1[l * 3 + k]]);
        #pragma unroll
        for (int k = 0; k < 8; k++) m = fmaxf(m, rm[iv[l * 8 + k]]);
        float xs = 127.f / fmaxf(m, EPSV);
        sxs = xs;
        if (j == 0) g_xs[tok] = xs;
    }
    __syncthreads();
    float xs = sxs;
    int src;
    if (j == 0)      src = l;
    else if (j < 4)  src = i0[l * 3 + (j - 1)];
    else if (j < 7)  src = i1[l * 3 + (j - 4)];
    else             src = iv[l * 8 + (j - 7)];
    const float* xr = g_xn + (size_t)(bb * LL + src) * DD;
    int d = threadIdx.x * 4;
    float4 f = *(const float4*)(xr + d);
    *(int*)&g_cq[(size_t)tok * K1 + j * DD + d] = quantPack4(f, xs);
}

// ---------------- LN2 + quantize ---------------------------------------------
__global__ void ln2q_kernel(const float* __restrict__ w,
                            const float* __restrict__ b) {
    __shared__ float red[256];
    int row = blockIdx.x;
    const float* xr = g_xres + (size_t)row * DD;
    int d = threadIdx.x * 4;
    float4 f = *(const float4*)(xr + d);
    float s  = f.x + f.y + f.z + f.w;
    float s2 = f.x*f.x + f.y*f.y + f.z*f.z + f.w*f.w;
    s  = blockReduceSum256(s, red);
    s2 = blockReduceSum256(s2, red);
    float mean = s * (1.f / DD);
    float var  = fmaxf(s2 * (1.f / DD) - mean * mean, 0.f);
    float rstd = rsqrtf(var + EPSV);
    float4 wv = *(const float4*)(w + d);
    float4 bv = *(const float4*)(b + d);
    float4 y;
    y.x = (f.x - mean) * rstd * wv.x + bv.x;
    y.y = (f.y - mean) * rstd * wv.y + bv.y;
    y.z = (f.z - mean) * rstd * wv.z + bv.z;
    y.w = (f.w - mean) * rstd * wv.w + bv.w;
    float mx = fmaxf(fmaxf(fabsf(y.x), fabsf(y.y)), fmaxf(fabsf(y.z), fabsf(y.w)));
    mx = blockReduceMax256(mx, red);
    float hs = 127.f / fmaxf(mx, EPSV);
    if (threadIdx.x == 0) g_hs[row] = hs;
    *(int*)&g_hq[(size_t)row * DD + d] = quantPack4(y, hs);
}

// ---------------- quantize gelu rows (4096 wide) ------------------------------
__global__ void geluq_kernel() {
    __shared__ float red[256];
    int row = blockIdx.x;
    const float* gr = g_gelu + (size_t)row * N2;
    float4 f[4];
    float mx = 0.f;
    #pragma unroll
    for (int ck = 0; ck < 4; ck++) {
        f[ck] = *(const float4*)(gr + ck * 1024 + threadIdx.x * 4);
        mx = fmaxf(mx, fmaxf(fmaxf(fabsf(f[ck].x), fabsf(f[ck].y)),
                             fmaxf(fabsf(f[ck].z), fabsf(f[ck].w))));
    }
    mx = blockReduceMax256(mx, red);
    float gs = 127.f / fmaxf(mx, EPSV);
    if (threadIdx.x == 0) g_gs[row] = gs;
    #pragma unroll
    for (int ck = 0; ck < 4; ck++)
        *(int*)&g_gq[(size_t)row * N2 + ck * 1024 + threadIdx.x * 4] =
            quantPack4(f[ck], gs);
}

// ---------------- IMMA GEMM: C[m,n] = sum_k A[m,k]*B[n,k] ---------------------
// R10-proven configuration, restored verbatim:
// 128x128 CTA tile, 8 warps 2(M)x4(N), warp tile 64x32, K-chunk 64 int8,
// 80B pitch (20-bank row stride: 8 consecutive rows cover 32 banks ->
// conflict-free ldmatrix), 2-stage cp.async (load next chunk, WAIT1, two
// __syncthreads per chunk). Occupancy 2 CTAs/SM.
// MODE 1: out = x    + acc*ws0/xs -> g_xres
// MODE 2: out = gelu(acc*ws1/hs)  -> g_gelu
// MODE 3: out = xres + acc*ws2/gs -> d_out
#define PITCH 80
#define BUF_A (128 * PITCH)             // 10240
#define GEMM_SMEM 40960                 // 2 stages x (A 10240 + B 10240)

__device__ __forceinline__ void mma_s8(int* d, const int* a, const int* b) {
    asm volatile(
        "mma.sync.aligned.m16n8k32.row.col.s32.s8.s8.s32 "
        "{%0,%1,%2,%3},{%4,%5,%6,%7},{%8,%9},{%0,%1,%2,%3};\n"
        : "+r"(d[0]), "+r"(d[1]), "+r"(d[2]), "+r"(d[3])
        : "r"(a[0]), "r"(a[1]), "r"(a[2]), "r"(a[3]), "r"(b[0]), "r"(b[1]));
}

template <int MODE>
__global__ __launch_bounds__(256, 2)
void gemm_u(const float* __restrict__ ext_add, float* __restrict__ ext_out) {
    constexpr int NTOT = (MODE == 2) ? N2 : DD;
    constexpr int K    = (MODE == 1) ? K1 : ((MODE == 2) ? DD : N2);
    constexpr int NCHUNK = K / 64;
    const signed char* A = (MODE == 1) ? g_cq  : (MODE == 2) ? g_hq  : g_gq;
    const signed char* B = (MODE == 1) ? g_wgq : (MODE == 2) ? g_w1q : g_w2q;
    const float* xsArr = (MODE == 1) ? g_xs : (MODE == 2) ? g_hs : g_gs;
    float* Out         = (MODE == 1) ? g_xres : (MODE == 2) ? g_gelu : ext_out;
    const float* Add   = (MODE == 1) ? ext_add : (MODE == 3) ? g_xres : nullptr;
    float ws = g_ws[MODE - 1];

    extern __shared__ char smem[];
    uint32_t sb = smem_u32(smem);
    int t = threadIdx.x;
    int warp = t >> 5, lane = t & 31;
    int m0 = blockIdx.y * 128, n0 = blockIdx.x * 128;

    int wm = warp >> 2, wn = warp & 3;
    int lr = lane & 7, hi8 = (lane >> 3) & 1, kh = (lane >> 4) & 1;
    uint32_t aBase = sb + (uint32_t)((wm * 64 + lr + hi8 * 8) * PITCH + kh * 16);
    uint32_t bBase = sb + 2u * BUF_A + (uint32_t)((wn * 32 + lr) * PITCH + hi8 * 16);

    // stage a 128x64-int8 tile of A and of B into buffer p (A: 0/10240; B: 20480/30720)
    auto loadI = [&](int kt, int p) {
        #pragma unroll
        for (int i = 0; i < 2; i++) {
            int id = t + 256 * i;
            int r = id >> 2, s = id & 3;
            const signed char* sa = &A[(size_t)(m0 + r) * K + kt + s * 16];
            CP_ASYNC16(sb + (uint32_t)(p * BUF_A + r * PITCH + s * 16),
                       (const void*)__cvta_generic_to_global(sa));
            const signed char* sbp = &B[(size_t)(n0 + r) * K + kt + s * 16];
            CP_ASYNC16(sb + (uint32_t)(2 * BUF_A + p * BUF_A + r * PITCH + s * 16),
                       (const void*)__cvta_generic_to_global(sbp));
        }
        CP_COMMIT();
    };

    int c[4][4][4];
    #pragma unroll
    for (int mi = 0; mi < 4; mi++)
        #pragma unroll
        for (int nj = 0; nj < 4; nj++)
            #pragma unroll
            for (int r = 0; r < 4; r++) c[mi][nj][r] = 0;

    loadI(0, 0);
    for (int ch = 0; ch < NCHUNK; ch++) {
        int p = ch & 1;
        if (ch + 1 < NCHUNK) { loadI((ch + 1) * 64, 1 - p); CP_WAIT1(); }
        else                 { CP_WAIT0(); }
        __syncthreads();
        uint32_t pOff = (uint32_t)(p * BUF_A);
        #pragma unroll
        for (int kk = 0; kk < 64; kk += 32) {
            int a[4][4];
            #pragma unroll
            for (int mi = 0; mi < 4; mi++) {
                uint32_t ad = aBase + pOff + (uint32_t)(mi * 16 * PITCH + kk);
                asm volatile(
                    "ldmatrix.sync.aligned.m8n8.x4.shared.b16 {%0,%1,%2,%3}, [%4];"
                    : "=r"(a[mi][0]), "=r"(a[mi][1]), "=r"(a[mi][2]), "=r"(a[mi][3])
                    : "r"(ad));
            }
            #pragma unroll
            for (int nj = 0; nj < 4; nj++) {
                int b[2];
                uint32_t bd = bBase + pOff + (uint32_t)(nj * 8 * PITCH + kk);
                asm volatile(
                    "ldmatrix.sync.aligned.m8n8.x2.shared.b16 {%0,%1}, [%2];"
                    : "=r"(b[0]), "=r"(b[1])
                    : "r"(bd));
                #pragma unroll
                for (int mi = 0; mi < 4; mi++)
                    mma_s8(c[mi][nj], a[mi], b);
            }
        }
        __syncthreads();
    }

    // epilogue: C frag rows (lane>>2)+{0,8}, cols (lane&3)*2+{0,1}
    int qr = lane >> 2, qc = (lane & 3) * 2;
    #pragma unroll
    for (int mi = 0; mi < 4; mi++) {
        int r0 = m0 + wm * 64 + mi * 16 + qr;
        float sc0 = ws / xsArr[r0];
        float sc1 = ws / xsArr[r0 + 8];
        #pragma unroll
        for (int nj = 0; nj < 4; nj++) {
            int n = n0 + wn * 32 + nj * 8 + qc;
            size_t off0 = (size_t)r0 * NTOT + n;
            size_t off1 = (size_t)(r0 + 8) * NTOT + n;
            float v00 = (float)c[mi][nj][0] * sc0;
            float v01 = (float)c[mi][nj][1] * sc0;
            float v10 = (float)c[mi][nj][2] * sc1;
            float v11 = (float)c[mi][nj][3] * sc1;
            if (MODE == 2) {
                float2 o0, o1;
                o0.x = 0.5f * v00 * (1.0f + erff(v00 * 0.70710678118654752f));
                o0.y = 0.5f * v01 * (1.0f + erff(v01 * 0.70710678118654752f));
                o1.x = 0.5f * v10 * (1.0f + erff(v10 * 0.70710678118654752f));
                o1.y = 0.5f * v11 * (1.0f + erff(v11 * 0.70710678118654752f));
                *(float2*)&Out[off0] = o0;
                *(float2*)&Out[off1] = o1;
            } else {
                float2 a0 = *(const float2*)&Add[off0];
                float2 a1 = *(const float2*)&Add[off1];
                float2 o0, o1;
                o0.x = a0.x + v00; o0.y = a0.y + v01;
                o1.x = a1.x + v10; o1.y = a1.y + v11;
                *(float2*)&Out[off0] = o0;
                *(float2*)&Out[off1] = o1;
            }
        }
    }
}

// ---------------- launch ------------------------------------------------------
extern "C" void kernel_launch(void* const* d_in, const int* in_sizes, int n_in,
                              void* d_out, int out_size) {
    const float* x    = (const float*)d_in[0];
    const float* ln1w = (const float*)d_in[1];
    const float* ln1b = (const float*)d_in[2];
    const float* ln2w = (const float*)d_in[3];
    const float* ln2b = (const float*)d_in[4];
    const float* Wg   = (const float*)d_in[5];
    const float* W1   = (const float*)d_in[6];
    const float* W2   = (const float*)d_in[7];
    const int* idx0   = (const int*)d_in[8];
    const int* idx1   = (const int*)d_in[9];
    const int* idxv   = (const int*)d_in[10];
    float* out = (float*)d_out;

    cudaFuncSetAttribute(gemm_u<1>, cudaFuncAttributeMaxDynamicSharedMemorySize, GEMM_SMEM);
    cudaFuncSetAttribute(gemm_u<2>, cudaFuncAttributeMaxDynamicSharedMemorySize, GEMM_SMEM);
    cudaFuncSetAttribute(gemm_u<3>, cudaFuncAttributeMaxDynamicSharedMemorySize, GEMM_SMEM);

    const int quantBlocks = (NWG + NW1 + NW2) / 4 / 256;   // exact multiple

    // Launch order: gemm_u<1> is the 6th launch -> captured by ncu -s 5 -c 1.
    absmean_partial_all<<<dim3(512, 3), 256>>>(Wg, W1, W2);          // 1
    absmean_final_all<<<3, 512>>>();                                 // 2
    quant_w_all<<<quantBlocks, 256>>>(Wg, W1, W2);                   // 3
    ln1_kernel<<<MTOT, 256>>>(x, ln1w, ln1b);                        // 4
    buildc_kernel<<<MTOT * 15, 256>>>(idx0, idx1, idxv);             // 5
    gemm_u<1><<<dim3(DD / 128, MTOT / 128), 256, GEMM_SMEM>>>(x, nullptr);       // 6 <- profiled
    ln2q_kernel<<<MTOT, 256>>>(ln2w, ln2b);                          // 7
    gemm_u<2><<<dim3(N2 / 128, MTOT / 128), 256, GEMM_SMEM>>>(nullptr, nullptr); // 8
    geluq_kernel<<<MTOT, 256>>>();                                   // 9
    gemm_u<3><<<dim3(DD / 128, MTOT / 128), 256, GEMM_SMEM>>>(nullptr, out);     // 10
}

// round 17
// speedup vs baseline: 4.3489x; 4.3489x over previous
#include <cuda_runtime.h>
#include <cuda_bf16.h>
#include <math.h>
#include <stdint.h>

// Problem dims (fixed by the dataset)
#define BB   32
#define LL   256
#define DD   1024
#define MTOT (BB*LL)      // 8192 tokens
#define K1   (15*DD)      // 15360
#define N2   (4*DD)       // 4096
#define EPSV 1e-5f

#define NWG (DD*K1)       // 15,728,640
#define NW1 (N2*DD)       // 4,194,304
#define NW2 (DD*N2)       // 4,194,304

typedef __nv_bfloat16 bf16;

// tcgen05 available only in the sm_103a SASS pass; the compute_103 PTX pass
// compiles the IMMA fallback. The driver runs the sm_103a SASS on GB300, so
// the tcgen05 path is what executes. DO NOT REMOVE THIS GUARD.
#if defined(__CUDA_ARCH_FEAT_SM103_ALL) || defined(__CUDA_ARCH_FEAT_SM100_ALL)
#define HAS_TC 1
#else
#define HAS_TC 0
#endif

// ---------------- scratch (device globals; no allocation allowed) -----------
// Quantized buffers sized for the larger (bf16) element; int8 path uses half.
__device__ float g_xn[MTOT*DD];
__device__ float g_rowmax[MTOT];
__device__ float g_xs[MTOT];
__device__ float g_hs[MTOT];
__device__ float g_gs[MTOT];
__device__ float g_xres[MTOT*DD];
__device__ float g_gelu[MTOT*N2];
__device__ __align__(16) unsigned char g_cq_raw[(size_t)MTOT*K1*2];
__device__ __align__(16) unsigned char g_hq_raw[(size_t)MTOT*DD*2];
__device__ __align__(16) unsigned char g_gq_raw[(size_t)MTOT*N2*2];
__device__ __align__(16) unsigned char g_wgq_raw[(size_t)NWG*2];
__device__ __align__(16) unsigned char g_w1q_raw[(size_t)NW1*2];
__device__ __align__(16) unsigned char g_w2q_raw[(size_t)NW2*2];
__device__ float g_ws[3];
__device__ float g_part[3][512];

// ---------------- small helpers ---------------------------------------------
__device__ __forceinline__ float blockReduceSum256(float v, float* red) {
    int t = threadIdx.x;
    red[t] = v; __syncthreads();
    #pragma unroll
    for (int o = 128; o > 0; o >>= 1) {
        if (t < o) red[t] += red[t + o];
        __syncthreads();
    }
    float r = red[0]; __syncthreads();
    return r;
}
__device__ __forceinline__ float blockReduceMax256(float v, float* red) {
    int t = threadIdx.x;
    red[t] = v; __syncthreads();
    #pragma unroll
    for (int o = 128; o > 0; o >>= 1) {
        if (t < o) red[t] = fmaxf(red[t], red[t + o]);
        __syncthreads();
    }
    float r = red[0]; __syncthreads();
    return r;
}
__device__ __forceinline__ uint32_t smem_u32(const void* p) {
    return (uint32_t)__cvta_generic_to_shared(p);
}
__device__ __forceinline__ uint32_t packbf2(float lo, float hi) {
    uint32_t r;
    asm("cvt.rn.bf16x2.f32 %0, %1, %2;" : "=r"(r) : "f"(hi), "f"(lo));
    return r;
}
// round-half-even quantize to [-128,127]
__device__ __forceinline__ int4 quantI4(float4 f, float s) {
    int4 q;
    q.x = min(max(__float2int_rn(f.x * s), -128), 127);
    q.y = min(max(__float2int_rn(f.y * s), -128), 127);
    q.z = min(max(__float2int_rn(f.z * s), -128), 127);
    q.w = min(max(__float2int_rn(f.w * s), -128), 127);
    return q;
}
// store 4 quantized values at element index idx (format per active path)
__device__ __forceinline__ void storeQ4(unsigned char* buf, size_t idx, int4 q) {
#if HAS_TC
    uint2 r;
    r.x = packbf2((float)q.x, (float)q.y);
    r.y = packbf2((float)q.z, (float)q.w);
    *(uint2*)(buf + idx * 2) = r;
#else
    *(int*)(buf + idx) = (q.x & 255) | ((q.y & 255) << 8) |
                         ((q.z & 255) << 16) | ((q.w & 255) << 24);
#endif
}

#define SW128F(off) ((off) ^ (((off) >> 3) & 0x70))
#define CP_ASYNC16(dst, src) \
    asm volatile("cp.async.cg.shared.global [%0], [%1], 16;\n" :: "r"(dst), "l"(src))
#define CP_COMMIT() asm volatile("cp.async.commit_group;\n" ::: "memory")
#define CP_WAIT0()  asm volatile("cp.async.wait_group 0;\n" ::: "memory")
#define CP_WAIT1()  asm volatile("cp.async.wait_group 1;\n" ::: "memory")

// ---------------- weight quantization (merged, 3 slots) ----------------------
__global__ void absmean_partial_all(const float* __restrict__ Wg,
                                    const float* __restrict__ W1,
                                    const float* __restrict__ W2) {
    __shared__ float red[256];
    int slot = blockIdx.y;
    const float* W = (slot == 0) ? Wg : (slot == 1) ? W1 : W2;
    int n = (slot == 0) ? NWG : (slot == 1) ? NW1 : NW2;
    float s = 0.f;
    for (int i = blockIdx.x * blockDim.x + threadIdx.x; i < n; i += 512 * blockDim.x)
        s += fabsf(W[i]);
    red[threadIdx.x] = s; __syncthreads();
    #pragma unroll
    for (int o = 128; o > 0; o >>= 1) {
        if (threadIdx.x < o) red[threadIdx.x] += red[threadIdx.x + o];
        __syncthreads();
    }
    if (threadIdx.x == 0) g_part[slot][blockIdx.x] = red[0];
}
__global__ void absmean_final_all() {
    __shared__ float red[512];
    int slot = blockIdx.x;
    red[threadIdx.x] = g_part[slot][threadIdx.x]; __syncthreads();
    #pragma unroll
    for (int o = 256; o > 0; o >>= 1) {
        if (threadIdx.x < o) red[threadIdx.x] += red[threadIdx.x + o];
        __syncthreads();
    }
    float invn = (slot == 0) ? (1.0f / (float)NWG)
               : (slot == 1) ? (1.0f / (float)NW1) : (1.0f / (float)NW2);
    if (threadIdx.x == 0) g_ws[slot] = red[0] * invn + EPSV;
}
__global__ void quant_w_all(const float* __restrict__ Wg,
                            const float* __restrict__ W1,
                            const float* __restrict__ W2) {
    int i = (blockIdx.x * blockDim.x + threadIdx.x) * 4;
    const float* W;
    unsigned char* outp;
    float ws;
    if (i < NWG)            { W = Wg;                 outp = g_wgq_raw; ws = g_ws[0]; }
    else if (i < NWG + NW1) { W = W1; i -= NWG;       outp = g_w1q_raw; ws = g_ws[1]; }
    else                    { W = W2; i -= NWG + NW1; outp = g_w2q_raw; ws = g_ws[2];
                              if (i >= NW2) return; }
    float4 f = *(const float4*)(W + i);
    int4 q;
    q.x = min(max(__float2int_rn(f.x / ws), -1), 1);
    q.y = min(max(__float2int_rn(f.y / ws), -1), 1);
    q.z = min(max(__float2int_rn(f.z / ws), -1), 1);
    q.w = min(max(__float2int_rn(f.w / ws), -1), 1);
    storeQ4(outp, (size_t)i, q);
}

// ---------------- LN1: stats + output + per-row max --------------------------
__global__ void ln1_kernel(const float* __restrict__ x,
                           const float* __restrict__ w,
                           const float* __restrict__ b) {
    __shared__ float red[256];
    int row = blockIdx.x;
    const float* xr = x + (size_t)row * DD;
    int d = threadIdx.x * 4;
    float4 f = *(const float4*)(xr + d);
    float s  = f.x + f.y + f.z + f.w;
    float s2 = f.x*f.x + f.y*f.y + f.z*f.z + f.w*f.w;
    s  = blockReduceSum256(s, red);
    s2 = blockReduceSum256(s2, red);
    float mean = s * (1.f / DD);
    float var  = fmaxf(s2 * (1.f / DD) - mean * mean, 0.f);
    float rstd = rsqrtf(var + EPSV);
    float4 wv = *(const float4*)(w + d);
    float4 bv = *(const float4*)(b + d);
    float4 y;
    y.x = (f.x - mean) * rstd * wv.x + bv.x;
    y.y = (f.y - mean) * rstd * wv.y + bv.y;
    y.z = (f.z - mean) * rstd * wv.z + bv.z;
    y.w = (f.w - mean) * rstd * wv.w + bv.w;
    *(float4*)&g_xn[(size_t)row * DD + d] = y;
    float mx = fmaxf(fmaxf(fabsf(y.x), fabsf(y.y)), fmaxf(fabsf(y.z), fabsf(y.w)));
    mx = blockReduceMax256(mx, red);
    if (threadIdx.x == 0) g_rowmax[row] = mx;
}

// ---------------- build quantized combined (scale computed inline) -----------
__global__ void buildc_kernel(const int* __restrict__ i0,
                              const int* __restrict__ i1,
                              const int* __restrict__ iv) {
    __shared__ float sxs;
    int bid = blockIdx.x;
    int tok = bid / 15, j = bid % 15;
    int bb = tok / LL, l = tok % LL;
    if (threadIdx.x == 0) {
        const float* rm = g_rowmax + bb * LL;
        float m = rm[l];
        #pragma unroll
        for (int k = 0; k < 3; k++) m = fmaxf(m, rm[i0[l * 3 + k]]);
        #pragma unroll
        for (int k = 0; k < 3; k++) m = fmaxf(m, rm[i1[l * 3 + k]]);
        #pragma unroll
        for (int k = 0; k < 8; k++) m = fmaxf(m, rm[iv[l * 8 + k]]);
        float xs = 127.f / fmaxf(m, EPSV);
        sxs = xs;
        if (j == 0) g_xs[tok] = xs;
    }
    __syncthreads();
    float xs = sxs;
    int src;
    if (j == 0)      src = l;
    else if (j < 4)  src = i0[l * 3 + (j - 1)];
    else if (j < 7)  src = i1[l * 3 + (j - 4)];
    else             src = iv[l * 8 + (j - 7)];
    const float* xr = g_xn + (size_t)(bb * LL + src) * DD;
    int d = threadIdx.x * 4;
    float4 f = *(const float4*)(xr + d);
    storeQ4(g_cq_raw, (size_t)tok * K1 + j * DD + d, quantI4(f, xs));
}

// ---------------- LN2 + quantize ---------------------------------------------
__global__ void ln2q_kernel(const float* __restrict__ w,
                            const float* __restrict__ b) {
    __shared__ float red[256];
    int row = blockIdx.x;
    const float* xr = g_xres + (size_t)row * DD;
    int d = threadIdx.x * 4;
    float4 f = *(const float4*)(xr + d);
    float s  = f.x + f.y + f.z + f.w;
    float s2 = f.x*f.x + f.y*f.y + f.z*f.z + f.w*f.w;
    s  = blockReduceSum256(s, red);
    s2 = blockReduceSum256(s2, red);
    float mean = s * (1.f / DD);
    float var  = fmaxf(s2 * (1.f / DD) - mean * mean, 0.f);
    float rstd = rsqrtf(var + EPSV);
    float4 wv = *(const float4*)(w + d);
    float4 bv = *(const float4*)(b + d);
    float4 y;
    y.x = (f.x - mean) * rstd * wv.x + bv.x;
    y.y = (f.y - mean) * rstd * wv.y + bv.y;
    y.z = (f.z - mean) * rstd * wv.z + bv.z;
    y.w = (f.w - mean) * rstd * wv.w + bv.w;
    float mx = fmaxf(fmaxf(fabsf(y.x), fabsf(y.y)), fmaxf(fabsf(y.z), fabsf(y.w)));
    mx = blockReduceMax256(mx, red);
    float hs = 127.f / fmaxf(mx, EPSV);
    if (threadIdx.x == 0) g_hs[row] = hs;
    storeQ4(g_hq_raw, (size_t)row * DD + d, quantI4(y, hs));
}

// ---------------- quantize gelu rows (4096 wide) ------------------------------
__global__ void geluq_kernel() {
    __shared__ float red[256];
    int row = blockIdx.x;
    const float* gr = g_gelu + (size_t)row * N2;
    float4 f[4];
    float mx = 0.f;
    #pragma unroll
    for (int ck = 0; ck < 4; ck++) {
        f[ck] = *(const float4*)(gr + ck * 1024 + threadIdx.x * 4);
        mx = fmaxf(mx, fmaxf(fmaxf(fabsf(f[ck].x), fabsf(f[ck].y)),
                             fmaxf(fabsf(f[ck].z), fabsf(f[ck].w))));
    }
    mx = blockReduceMax256(mx, red);
    float gs = 127.f / fmaxf(mx, EPSV);
    if (threadIdx.x == 0) g_gs[row] = gs;
    #pragma unroll
    for (int ck = 0; ck < 4; ck++)
        storeQ4(g_gq_raw, (size_t)row * N2 + ck * 1024 + threadIdx.x * 4,
                quantI4(f[ck], gs));
}

// ---------------- unified GEMM: C[m,n] = sum_k A[m,k]*B[n,k] ------------------
// CTA tile 128(M) x 256(N), K-chunk 64, cp.async double-buffered.
// tcgen05 path (what actually runs): SS bf16, f32 TMEM accum (exact integer
// math), single 128x256 accumulator, idesc N=256. 2 CTAs/SM.
// Fallback path (compute_103 PTX pass only; never executes on GB300): IMMA,
// two sequential 128x128 n-halves.
// MODE 1: out = x    + acc*ws0/xs -> g_xres
// MODE 2: out = gelu(acc*ws1/hs)  -> g_gelu
// MODE 3: out = xres + acc*ws2/gs -> d_out
#define GEMM_SMEM 99328   // 1024 hdr + 2*16KB A + 2*32KB B

#if HAS_TC
__device__ __forceinline__ void mbar_init(uint32_t a, uint32_t cnt) {
    asm volatile("mbarrier.init.shared.b64 [%0], %1;" :: "r"(a), "r"(cnt) : "memory");
}
__device__ __forceinline__ void mbar_wait(uint32_t a, uint32_t parity) {
    asm volatile(
        "{\n\t.reg .pred P;\n"
        "LAB_%=:\n\t"
        "mbarrier.try_wait.parity.acquire.cta.shared::cta.b64 P, [%0], %1, 0x989680;\n\t"
        "@P bra DONE_%=;\n\t"
        "bra LAB_%=;\n"
        "DONE_%=:\n\t}"
        :: "r"(a), "r"(parity) : "memory");
}
__device__ __forceinline__ uint64_t make_desc(uint32_t addr) {
    return ((uint64_t)2 << 61) | ((uint64_t)1 << 46) | ((uint64_t)64 << 32) |
           ((uint64_t)1 << 16) | ((uint64_t)(addr >> 4) & 0x3FFF);
}
__device__ __forceinline__ void mma_f16_ss(uint32_t d, uint64_t ad, uint64_t bd,
                                           uint32_t idesc, uint32_t en) {
    asm volatile(
        "{\n\t.reg .pred p;\n\t"
        "setp.ne.u32 p, %4, 0;\n\t"
        "tcgen05.mma.cta_group::1.kind::f16 [%0], %1, %2, %3, {%5, %5, %5, %5}, p;\n\t}"
        :: "r"(d), "l"(ad), "l"(bd), "r"(idesc), "r"(en), "r"(0u) : "memory");
}
#else
__device__ __forceinline__ void mma_s8(int* d, const int* a, const int* b) {
    asm volatile(
        "mma.sync.aligned.m16n8k32.row.col.s32.s8.s8.s32 "
        "{%0,%1,%2,%3},{%4,%5,%6,%7},{%8,%9},{%0,%1,%2,%3};\n"
        : "+r"(d[0]), "+r"(d[1]), "+r"(d[2]), "+r"(d[3])
        : "r"(a[0]), "r"(a[1]), "r"(a[2]), "r"(a[3]), "r"(b[0]), "r"(b[1]));
}
#endif

template <int MODE>
__global__ __launch_bounds__(256, 2)
void gemm_u(const float* __restrict__ ext_add, float* __restrict__ ext_out) {
    constexpr int NTOT = (MODE == 2) ? N2 : DD;
    constexpr int K    = (MODE == 1) ? K1 : ((MODE == 2) ? DD : N2);
    constexpr int NCHUNK = K / 64;
    const unsigned char* Araw = (MODE == 1) ? g_cq_raw  : (MODE == 2) ? g_hq_raw  : g_gq_raw;
    const unsigned char* Braw = (MODE == 1) ? g_wgq_raw : (MODE == 2) ? g_w1q_raw : g_w2q_raw;
    const float* xsArr = (MODE == 1) ? g_xs : (MODE == 2) ? g_hs : g_gs;
    float* Out         = (MODE == 1) ? g_xres : (MODE == 2) ? g_gelu : ext_out;
    const float* Add   = (MODE == 1) ? ext_add : (MODE == 3) ? g_xres : nullptr;
    float ws = g_ws[MODE - 1];

    extern __shared__ char smem[];
    uint32_t sb = smem_u32(smem);
    int t = threadIdx.x;
    int warp = t >> 5, lane = t & 31;

#if HAS_TC
    // ---------------- tcgen05 path: 128(M) x 256(N) tile ---------------------
    const bf16* A = (const bf16*)Araw;
    const bf16* B = (const bf16*)Braw;
    int m0 = blockIdx.y * 128, n0 = blockIdx.x * 256;
    const uint32_t MBAR = sb + 16;
    const uint32_t AOFF = 1024;                 // 2 x 16384
    const uint32_t BOFF = 1024 + 32768;         // 2 x 32768

    if (warp == 0) {
        asm volatile("tcgen05.alloc.cta_group::1.sync.aligned.shared::cta.b32 [%0], %1;"
                     :: "r"(sb), "r"(256u) : "memory");
        asm volatile("tcgen05.relinquish_alloc_permit.cta_group::1.sync.aligned;");
    }
    if (t == 0) mbar_init(MBAR, 1);
    __syncthreads();
    uint32_t tmem;
    asm volatile("ld.shared.b32 %0, [%1];" : "=r"(tmem) : "r"(sb));

    // stage A 128x64 bf16 (16KB) + B 256x64 bf16 (32KB) per chunk, SW128
    auto loadTC = [&](int kt, int p) {
        #pragma unroll
        for (int i = 0; i < 4; i++) {
            int id = t + 256 * i;
            int r = id >> 3, s = id & 7;
            const char* sa = (const char*)(A + (size_t)(m0 + r) * K + kt) + s * 16;
            CP_ASYNC16(sb + AOFF + p * 16384 + SW128F(r * 128 + s * 16),
                       (const void*)__cvta_generic_to_global(sa));
        }
        #pragma unroll
        for (int i = 0; i < 8; i++) {
            int id = t + 256 * i;
            int r = id >> 3, s = id & 7;
            const char* sbp = (const char*)(B + (size_t)(n0 + r) * K + kt) + s * 16;
            CP_ASYNC16(sb + BOFF + p * 32768 + SW128F(r * 128 + s * 16),
                       (const void*)__cvta_generic_to_global(sbp));
        }
        CP_COMMIT();
    };

    // f32 acc, bf16 x bf16, N=256, M=128
    const uint32_t idesc = (1u << 4) | (1u << 7) | (1u << 10) |
                           (32u << 17) | (8u << 24);

    loadTC(0, 0);
    for (int c = 0; c < NCHUNK; c++) {
        int p = c & 1;
        if (c + 1 < NCHUNK) {
            if (c >= 1) mbar_wait(MBAR, (uint32_t)((c - 1) & 1)); // buf (c+1)&1 free
            loadTC((c + 1) * 64, 1 - p);
            CP_WAIT1();
        } else {
            CP_WAIT0();
        }
        asm volatile("fence.proxy.async.shared::cta;" ::: "memory");
        __syncthreads();
        if (t == 0) {
            uint64_t ad = make_desc(sb + AOFF + p * 16384);
            uint64_t bd = make_desc(sb + BOFF + p * 32768);
            #pragma unroll
            for (int s = 0; s < 4; s++)
                mma_f16_ss(tmem, ad + s * 2, bd + s * 2, idesc,
                           (c == 0 && s == 0) ? 0u : 1u);
            asm volatile(
                "tcgen05.commit.cta_group::1.mbarrier::arrive::one.shared::cluster.b64 [%0];"
                :: "r"(MBAR) : "memory");
        }
        __syncthreads();
    }
    mbar_wait(MBAR, (uint32_t)((NCHUNK - 1) & 1));
    asm volatile("tcgen05.fence::after_thread_sync;" ::: "memory");

    // epilogue: 8 warps; warp&3 = row subpartition, warp>>2 = column half
    {
        int part = warp & 3, half = warp >> 2;
        int row = m0 + part * 32 + lane;
        float sc = ws / xsArr[row];
        uint32_t tbase = tmem + half * 128;
        int nb = n0 + half * 128;
        #pragma unroll
        for (int cc = 0; cc < 4; cc++) {
            uint32_t r[32];
            asm volatile(
                "tcgen05.ld.sync.aligned.32x32b.x32.b32 "
                "{%0,%1,%2,%3,%4,%5,%6,%7,%8,%9,%10,%11,%12,%13,%14,%15,"
                "%16,%17,%18,%19,%20,%21,%22,%23,%24,%25,%26,%27,%28,%29,%30,%31}, [%32];"
                : "=r"(r[0]),  "=r"(r[1]),  "=r"(r[2]),  "=r"(r[3]),
                  "=r"(r[4]),  "=r"(r[5]),  "=r"(r[6]),  "=r"(r[7]),
                  "=r"(r[8]),  "=r"(r[9]),  "=r"(r[10]), "=r"(r[11]),
                  "=r"(r[12]), "=r"(r[13]), "=r"(r[14]), "=r"(r[15]),
                  "=r"(r[16]), "=r"(r[17]), "=r"(r[18]), "=r"(r[19]),
                  "=r"(r[20]), "=r"(r[21]), "=r"(r[22]), "=r"(r[23]),
                  "=r"(r[24]), "=r"(r[25]), "=r"(r[26]), "=r"(r[27]),
                  "=r"(r[28]), "=r"(r[29]), "=r"(r[30]), "=r"(r[31])
                : "r"(tbase + cc * 32));
            asm volatile("tcgen05.wait::ld.sync.aligned;" ::: "memory");
            size_t off = (size_t)row * NTOT + nb + cc * 32;
            if (MODE == 2) {
                #pragma unroll
                for (int j = 0; j < 32; j++) {
                    float v = __uint_as_float(r[j]) * sc;
                    Out[off + j] = 0.5f * v * (1.0f + erff(v * 0.70710678118654752f));
                }
            } else {
                #pragma unroll
                for (int j = 0; j < 32; j += 4) {
                    float4 a4 = *(const float4*)&Add[off + j];
                    float4 o;
                    o.x = a4.x + __uint_as_float(r[j + 0]) * sc;
                    o.y = a4.y + __uint_as_float(r[j + 1]) * sc;
                    o.z = a4.z + __uint_as_float(r[j + 2]) * sc;
                    o.w = a4.w + __uint_as_float(r[j + 3]) * sc;
                    *(float4*)&Out[off + j] = o;
                }
            }
        }
        asm volatile("tcgen05.fence::before_thread_sync;" ::: "memory");
    }
    __syncthreads();
    if (warp == 0)
        asm volatile("tcgen05.dealloc.cta_group::1.sync.aligned.b32 %0, %1;"
                     :: "r"(tmem), "r"(256u));
#else
    // ---------------- IMMA fallback (compile-only on GB300) ------------------
    const signed char* A = (const signed char*)Araw;
    const signed char* B = (const signed char*)Braw;
    int wm = warp >> 2, wn = warp & 3;
    int lr = lane & 7, hi8 = (lane >> 3) & 1, kh = (lane >> 4) & 1;
    uint32_t aBase = sb + (uint32_t)((wm * 64 + lr + hi8 * 8) * 80 + kh * 16);
    uint32_t bBase = sb + 20480u + (uint32_t)((wn * 32 + lr) * 80 + hi8 * 16);

    for (int qn = 0; qn < 2; qn++) {
        int m0 = blockIdx.y * 128, n0 = blockIdx.x * 256 + qn * 128;

        auto loadI = [&](int kt, int p) {
            #pragma unroll
            for (int i = 0; i < 2; i++) {
                int id = t + 256 * i;
                int r = id >> 2, s = id & 3;
                const signed char* sa = &A[(size_t)(m0 + r) * K + kt + s * 16];
                CP_ASYNC16(sb + p * 10240 + (uint32_t)(r * 80 + s * 16),
                           (const void*)__cvta_generic_to_global(sa));
                const signed char* sbp = &B[(size_t)(n0 + r) * K + kt + s * 16];
                CP_ASYNC16(sb + 20480u + p * 10240 + (uint32_t)(r * 80 + s * 16),
                           (const void*)__cvta_generic_to_global(sbp));
            }
            CP_COMMIT();
        };

        int c[4][4][4];
        #pragma unroll
        for (int mi = 0; mi < 4; mi++)
            #pragma unroll
            for (int nj = 0; nj < 4; nj++)
                #pragma unroll
                for (int r = 0; r < 4; r++) c[mi][nj][r] = 0;

        loadI(0, 0);
        for (int ch = 0; ch < NCHUNK; ch++) {
            int p = ch & 1;
            if (ch + 1 < NCHUNK) { loadI((ch + 1) * 64, 1 - p); CP_WAIT1(); }
            else                 { CP_WAIT0(); }
            __syncthreads();
            #pragma unroll
            for (int kk = 0; kk < 64; kk += 32) {
                int a[4][4];
                #pragma unroll
                for (int mi = 0; mi < 4; mi++) {
                    uint32_t ad = aBase + (uint32_t)(p * 10240 + mi * 16 * 80 + kk);
                    asm volatile(
                        "ldmatrix.sync.aligned.m8n8.x4.shared.b16 {%0,%1,%2,%3}, [%4];"
                        : "=r"(a[mi][0]), "=r"(a[mi][1]), "=r"(a[mi][2]), "=r"(a[mi][3])
                        : "r"(ad));
                }
                #pragma unroll
                for (int nj = 0; nj < 4; nj++) {
                    int b[2];
                    uint32_t bd = bBase + (uint32_t)(p * 10240 + nj * 8 * 80 + kk);
                    asm volatile(
                        "ldmatrix.sync.aligned.m8n8.x2.shared.b16 {%0,%1}, [%2];"
                        : "=r"(b[0]), "=r"(b[1])
                        : "r"(bd));
                    #pragma unroll
                    for (int mi = 0; mi < 4; mi++)
                        mma_s8(c[mi][nj], a[mi], b);
                }
            }
            __syncthreads();
        }

        int qr = lane >> 2, qc = (lane & 3) * 2;
        #pragma unroll
        for (int mi = 0; mi < 4; mi++) {
            int r0 = m0 + wm * 64 + mi * 16 + qr;
            float sc0 = ws / xsArr[r0];
            float sc1 = ws / xsArr[r0 + 8];
            #pragma unroll
            for (int nj = 0; nj < 4; nj++) {
                int n = n0 + wn * 32 + nj * 8 + qc;
                size_t off0 = (size_t)r0 * NTOT + n;
                size_t off1 = (size_t)(r0 + 8) * NTOT + n;
                float v00 = (float)c[mi][nj][0] * sc0;
                float v01 = (float)c[mi][nj][1] * sc0;
                float v10 = (float)c[mi][nj][2] * sc1;
                float v11 = (float)c[mi][nj][3] * sc1;
                if (MODE == 2) {
                    float2 o0, o1;
                    o0.x = 0.5f * v00 * (1.0f + erff(v00 * 0.70710678118654752f));
                    o0.y = 0.5f * v01 * (1.0f + erff(v01 * 0.70710678118654752f));
                    o1.x = 0.5f * v10 * (1.0f + erff(v10 * 0.70710678118654752f));
                    o1.y = 0.5f * v11 * (1.0f + erff(v11 * 0.70710678118654752f));
                    *(float2*)&Out[off0] = o0;
                    *(float2*)&Out[off1] = o1;
                } else {
                    float2 a0 = *(const float2*)&Add[off0];
                    float2 a1 = *(const float2*)&Add[off1];
                    float2 o0, o1;
                    o0.x = a0.x + v00; o0.y = a0.y + v01;
                    o1.x = a1.x + v10; o1.y = a1.y + v11;
                    *(float2*)&Out[off0] = o0;
                    *(float2*)&Out[off1] = o1;
                }
            }
        }
        __syncthreads();
    }
#endif
}

// ---------------- launch ------------------------------------------------------
extern "C" void kernel_launch(void* const* d_in, const int* in_sizes, int n_in,
                              void* d_out, int out_size) {
    const float* x    = (const float*)d_in[0];
    const float* ln1w = (const float*)d_in[1];
    const float* ln1b = (const float*)d_in[2];
    const float* ln2w = (const float*)d_in[3];
    const float* ln2b = (const float*)d_in[4];
    const float* Wg   = (const float*)d_in[5];
    const float* W1   = (const float*)d_in[6];
    const float* W2   = (const float*)d_in[7];
    const int* idx0   = (const int*)d_in[8];
    const int* idx1   = (const int*)d_in[9];
    const int* idxv   = (const int*)d_in[10];
    float* out = (float*)d_out;

    cudaFuncSetAttribute(gemm_u<1>, cudaFuncAttributeMaxDynamicSharedMemorySize, GEMM_SMEM);
    cudaFuncSetAttribute(gemm_u<2>, cudaFuncAttributeMaxDynamicSharedMemorySize, GEMM_SMEM);
    cudaFuncSetAttribute(gemm_u<3>, cudaFuncAttributeMaxDynamicSharedMemorySize, GEMM_SMEM);

    const int quantBlocks = (NWG + NW1 + NW2) / 4 / 256;   // exact multiple

    // Launch order: gemm_u<1> is the 6th launch -> captured by ncu -s 5 -c 1.
    absmean_partial_all<<<dim3(512, 3), 256>>>(Wg, W1, W2);          // 1
    absmean_final_all<<<3, 512>>>();                                 // 2
    quant_w_all<<<quantBlocks, 256>>>(Wg, W1, W2);                   // 3
    ln1_kernel<<<MTOT, 256>>>(x, ln1w, ln1b);                        // 4
    buildc_kernel<<<MTOT * 15, 256>>>(idx0, idx1, idxv);             // 5
    gemm_u<1><<<dim3(DD / 256, MTOT / 128), 256, GEMM_SMEM>>>(x, nullptr);       // 6 <- profiled
    ln2q_kernel<<<MTOT, 256>>>(ln2w, ln2b);                          // 7
    gemm_u<2><<<dim3(N2 / 256, MTOT / 128), 256, GEMM_SMEM>>>(nullptr, nullptr); // 8
    geluq_kernel<<<MTOT, 256>>>();                                   // 9
    gemm_u<3><<<dim3(DD / 256, MTOT / 128), 256, GEMM_SMEM>>>(nullptr, out);     // 10
}